// round 4
// baseline (speedup 1.0000x reference)
#include <cuda_runtime.h>
#include <math.h>

#define SEQ 4096
#define INP 457
#define EMB 2048
#define G4E 8192
#define G4I 1828
#define NCTA 128
#define DCTA 115

__device__ float g_gx[(size_t)SEQ * G4E];    // Wih@x + biases, per timestep
__device__ float g_wihT[(size_t)INP * G4E];  // enc_Wih transposed
__device__ float g_weff[(size_t)G4I * INP];  // (dec_Wih+dec_Whh)@dec_Whr
__device__ float g_g0[G4I];                  // decoder step-0 gates
__device__ float g_h[2 * EMB];               // encoder hidden, double-buffered
__device__ float g_hraw[2 * INP];            // decoder raw hidden, double-buffered
__device__ volatile unsigned g_arr_enc[NCTA];
__device__ volatile unsigned g_arr_dec[NCTA];
__device__ volatile unsigned g_rel_enc;
__device__ volatile unsigned g_rel_dec;

__device__ __forceinline__ float sigf(float x) { return 1.0f / (1.0f + expf(-x)); }

// Flag-array grid barrier (CG-style: fence -> arrive -> block0 polls -> release).
__device__ __forceinline__ void gbar(volatile unsigned* arr, volatile unsigned* rel,
                                     unsigned s, int b, int tid, int n) {
  __threadfence();
  __syncthreads();
  if (b == 0) {
    if (tid == 0) arr[0] = s;
    for (int i = tid; i < n; i += blockDim.x) { while (arr[i] < s) {} }
    __syncthreads();
    if (tid == 0) { *rel = s; }
  } else {
    if (tid == 0) { arr[b] = s; while (*rel < s) {} __threadfence(); }
    __syncthreads();
  }
}

__global__ void init_kernel() {
  int i = blockIdx.x * blockDim.x + threadIdx.x;
  if (i < NCTA) { g_arr_enc[i] = 0u; g_arr_dec[i] = 0u; }
  if (i == 0)   { g_rel_enc = 0u; g_rel_dec = 0u; }
  if (i < EMB)  g_h[i] = 0.0f;  // encoder reads buffer 0 at t=0
}

// Transpose enc_Wih [8192][457] -> g_wihT [457][8192]
__global__ void tr_kernel(const float* __restrict__ in) {
  __shared__ float tile[32][33];
  int r0 = blockIdx.x * 32, c0 = blockIdx.y * 32;
  int x = threadIdx.x;
  for (int y = threadIdx.y; y < 32; y += 8) {
    int c = c0 + x;
    if (c < INP) tile[y][x] = in[(size_t)(r0 + y) * INP + c];
  }
  __syncthreads();
  for (int y = threadIdx.y; y < 32; y += 8) {
    int c = c0 + y;
    if (c < INP) g_wihT[(size_t)c * G4E + r0 + x] = tile[x][y];
  }
}

// Gx[t][r] = sum_k x[t][k]*Wih[r][k] + bih[r] + bhh[r]
// grid (32 row-blocks, 256 time-blocks), 256 thr; thread: 1 row x 16 timesteps.
__global__ void __launch_bounds__(256) gx_kernel(const float* __restrict__ x,
                                                 const float* __restrict__ bih,
                                                 const float* __restrict__ bhh) {
  __shared__ float xs[INP * 20];  // [k][t] padded to 20 (16B-aligned float4, fewer bank conflicts)
  const int tid = threadIdx.x;
  const int rb = blockIdx.x * 256, tb = blockIdx.y * 16;
  for (int i = tid; i < 16 * INP; i += 256) {
    int tt = i / INP, k = i - tt * INP;
    xs[k * 20 + tt] = x[(size_t)(tb + tt) * INP + k];
  }
  __syncthreads();
  const int r = rb + tid;
  float acc[16];
#pragma unroll
  for (int j = 0; j < 16; j++) acc[j] = 0.0f;
  for (int k = 0; k < INP; k++) {
    float w = g_wihT[(size_t)k * G4E + r];
    const float4* xv = (const float4*)(xs + k * 20);
    float4 a = xv[0], b = xv[1], c = xv[2], d = xv[3];
    acc[0]  += w * a.x; acc[1]  += w * a.y; acc[2]  += w * a.z; acc[3]  += w * a.w;
    acc[4]  += w * b.x; acc[5]  += w * b.y; acc[6]  += w * b.z; acc[7]  += w * b.w;
    acc[8]  += w * c.x; acc[9]  += w * c.y; acc[10] += w * c.z; acc[11] += w * c.w;
    acc[12] += w * d.x; acc[13] += w * d.y; acc[14] += w * d.z; acc[15] += w * d.w;
  }
  float bsum = bih[r] + bhh[r];
#pragma unroll
  for (int j = 0; j < 16; j++) g_gx[(size_t)(tb + j) * G4E + r] = acc[j] + bsum;
}

// W_eff[r][j] = sum_m (dWih[r][m]+dWhh[r][m]) * dWhr[m][j]
// grid 457 blocks x 128 thr; block: 4 rows, thread: 4 cols.
__global__ void weff_kernel(const float* __restrict__ dwih,
                            const float* __restrict__ dwhh,
                            const float* __restrict__ whr) {
  __shared__ float wcs[4 * 128];
  const int tid = threadIdx.x;
  const int r0 = blockIdx.x * 4;
  float acc[4][4];
#pragma unroll
  for (int i = 0; i < 4; i++)
#pragma unroll
    for (int j = 0; j < 4; j++) acc[i][j] = 0.0f;

  for (int kb = 0; kb < EMB; kb += 128) {
    __syncthreads();
#pragma unroll
    for (int i = 0; i < 4; i++) {
      size_t idx = (size_t)(r0 + i) * EMB + kb + tid;
      wcs[i * 128 + tid] = dwih[idx] + dwhh[idx];
    }
    __syncthreads();
    for (int kk = 0; kk < 128; kk++) {
      const float* wrow = whr + (size_t)(kb + kk) * INP;
      float v0 = wrow[tid];
      float v1 = wrow[tid + 128];
      float v2 = wrow[tid + 256];
      float v3 = (tid < 73) ? wrow[tid + 384] : 0.0f;
#pragma unroll
      for (int i = 0; i < 4; i++) {
        float w = wcs[i * 128 + kk];
        acc[i][0] += w * v0; acc[i][1] += w * v1;
        acc[i][2] += w * v2; acc[i][3] += w * v3;
      }
    }
  }
#pragma unroll
  for (int i = 0; i < 4; i++) {
    size_t rb = (size_t)(r0 + i) * INP;
    g_weff[rb + tid]       = acc[i][0];
    g_weff[rb + tid + 128] = acc[i][1];
    g_weff[rb + tid + 256] = acc[i][2];
    if (tid < 73) g_weff[rb + tid + 384] = acc[i][3];
  }
}

// Persistent encoder: 128 CTAs, CTA b owns hidden elems [16b,16b+16) -> 64 gate rows.
// Warp computes 8 rows; first 3 rows/warp (24/CTA = 192KB) L1-cached, rest __ldcg-streamed.
__global__ void __launch_bounds__(256, 1) enc_kernel(const float* __restrict__ whh) {
  __shared__ float hs[EMB];
  __shared__ float gsum[64];
  const int tid = threadIdx.x, wid = tid >> 5, lane = tid & 31, b = blockIdx.x;
  float c = 0.0f;
  unsigned s = 0;
  float4* hs4 = (float4*)hs;

  for (int t = 0; t < SEQ; t++) {
    float gx0 = 0.f, gx1 = 0.f, gx2 = 0.f, gx3 = 0.f;
    if (tid < 16) {
      size_t base = (size_t)t * G4E + (b << 4) + tid;
      gx0 = __ldcg(&g_gx[base]);
      gx1 = __ldcg(&g_gx[base + 2048]);
      gx2 = __ldcg(&g_gx[base + 4096]);
      gx3 = __ldcg(&g_gx[base + 6144]);
    }
    const float4* h4 = (const float4*)(g_h + (t & 1) * EMB);
    for (int i = tid; i < EMB / 4; i += 256) hs4[i] = __ldcg(h4 + i);
    __syncthreads();

#pragma unroll
    for (int j = 0; j < 8; j++) {
      int l = wid * 8 + j;
      int q = l >> 4, eL = l & 15;
      int row = (q << 11) + (b << 4) + eL;
      const float4* wr = (const float4*)(whh + (size_t)row * EMB);
      float sum = 0.0f;
      if (j < 3) {
#pragma unroll 8
        for (int k = lane; k < EMB / 4; k += 32) {
          float4 w = wr[k];  // default-cached: stays L1-resident across steps
          float4 hv = hs4[k];
          sum += w.x * hv.x; sum += w.y * hv.y;
          sum += w.z * hv.z; sum += w.w * hv.w;
        }
      } else {
#pragma unroll 8
        for (int k = lane; k < EMB / 4; k += 32) {
          float4 w = __ldcg(wr + k);  // stream, L1-bypass
          float4 hv = hs4[k];
          sum += w.x * hv.x; sum += w.y * hv.y;
          sum += w.z * hv.z; sum += w.w * hv.w;
        }
      }
#pragma unroll
      for (int o = 16; o; o >>= 1) sum += __shfl_xor_sync(0xffffffffu, sum, o);
      if (lane == 0) gsum[l] = sum;
    }
    __syncthreads();

    if (tid < 16) {
      float gi = gsum[tid]      + gx0;
      float gf = gsum[16 + tid] + gx1;
      float gg = gsum[32 + tid] + gx2;
      float go = gsum[48 + tid] + gx3;
      c = sigf(gf) * c + sigf(gi) * tanhf(gg);
      g_h[((t + 1) & 1) * EMB + (b << 4) + tid] = sigf(go) * tanhf(c);
    }
    gbar(g_arr_enc, &g_rel_enc, ++s, b, tid, NCTA);
  }
}

// g0[r] = dec_Wih[r] . h_enc + bih[r] + bhh[r]   (h_enc = g_h buffer 0 after encoder)
__global__ void dec_g0_kernel(const float* __restrict__ dwih,
                              const float* __restrict__ bih,
                              const float* __restrict__ bhh) {
  int wid = threadIdx.x >> 5, lane = threadIdx.x & 31;
  int row = blockIdx.x * 8 + wid;
  if (row >= G4I) return;
  const float4* w = (const float4*)(dwih + (size_t)row * EMB);
  const float4* h = (const float4*)g_h;
  float sum = 0.0f;
  for (int k = lane; k < EMB / 4; k += 32) {
    float4 a = w[k], b = h[k];
    sum += a.x * b.x + a.y * b.y + a.z * b.z + a.w * b.w;
  }
#pragma unroll
  for (int o = 16; o; o >>= 1) sum += __shfl_xor_sync(0xffffffffu, sum, o);
  if (lane == 0) g_g0[row] = sum + bih[row] + bhh[row];
}

// Persistent decoder: 115 CTAs, CTA b owns elems {4b..4b+3} (16 gate rows, SMEM-resident W_eff).
__global__ void __launch_bounds__(256, 1) dec_kernel(const float* __restrict__ bih,
                                                     const float* __restrict__ bhh,
                                                     float* __restrict__ out) {
  __shared__ float ws[16 * INP];
  __shared__ float hrs[INP];
  __shared__ float bs[16];
  __shared__ float gsum[16];
  const int tid = threadIdx.x, wid = tid >> 5, lane = tid & 31, b = blockIdx.x;

  for (int idx = tid; idx < 16 * INP; idx += 256) {
    int l = idx / INP, k = idx - l * INP;
    int q = l >> 2, i = l & 3;
    int e = 4 * b + i; if (e >= INP) e = INP - 1;
    ws[l * INP + k] = g_weff[(size_t)(q * INP + e) * INP + k];
  }
  if (tid < 16) {
    int q = tid >> 2, i = tid & 3;
    int e = 4 * b + i; if (e >= INP) e = INP - 1;
    int r = q * INP + e;
    bs[tid] = bih[r] + bhh[r];
  }
  __syncthreads();

  float c = 0.0f;
  unsigned s = 0;
  for (int t = 0; t < SEQ; t++) {
    if (t > 0) {
      for (int k = tid; k < INP; k += 256) hrs[k] = __ldcg(&g_hraw[(t & 1) * INP + k]);
      __syncthreads();
#pragma unroll
      for (int j = 0; j < 2; j++) {
        int l = wid * 2 + j;
        const float* wr = ws + l * INP;
        float sum = 0.0f;
        for (int k = lane; k < INP; k += 32) sum += wr[k] * hrs[k];
#pragma unroll
        for (int o = 16; o; o >>= 1) sum += __shfl_xor_sync(0xffffffffu, sum, o);
        if (lane == 0) gsum[l] = sum;
      }
      __syncthreads();
    }
    if (tid < 4) {
      int e = 4 * b + tid;
      bool valid = (e < INP);
      int es = valid ? e : 0;
      float gi, gf, gg, go;
      if (t == 0) {
        gi = g_g0[es]; gf = g_g0[INP + es]; gg = g_g0[2 * INP + es]; go = g_g0[3 * INP + es];
      } else {
        gi = gsum[tid]     + bs[tid];
        gf = gsum[4 + tid] + bs[4 + tid];
        gg = gsum[8 + tid] + bs[8 + tid];
        go = gsum[12 + tid] + bs[12 + tid];
      }
      c = sigf(gf) * c + sigf(gi) * tanhf(gg);
      if (valid) {
        out[(size_t)(SEQ - 1 - t) * INP + e] = c;
        g_hraw[((t + 1) & 1) * INP + e] = sigf(go) * tanhf(c);
      }
    }
    gbar(g_arr_dec, &g_rel_dec, ++s, b, tid, DCTA);
  }
}

// In-place row softmax over d_out[4096][457]
__global__ void softmax_kernel(float* __restrict__ out) {
  __shared__ float red[32];
  const int t = blockIdx.x, tid = threadIdx.x, lane = tid & 31, wid = tid >> 5;
  float v = (tid < INP) ? out[(size_t)t * INP + tid] : -1e30f;
  float m = v;
#pragma unroll
  for (int o = 16; o; o >>= 1) m = fmaxf(m, __shfl_xor_sync(0xffffffffu, m, o));
  if (lane == 0) red[wid] = m;
  __syncthreads();
  m = -1e30f;
  for (int i = 0; i < 16; i++) m = fmaxf(m, red[i]);
  __syncthreads();
  float e = (tid < INP) ? expf(v - m) : 0.0f;
  float sum = e;
#pragma unroll
  for (int o = 16; o; o >>= 1) sum += __shfl_xor_sync(0xffffffffu, sum, o);
  if (lane == 0) red[wid] = sum;
  __syncthreads();
  sum = 0.0f;
  for (int i = 0; i < 16; i++) sum += red[i];
  if (tid < INP) out[(size_t)t * INP + tid] = e / sum;
}

extern "C" void kernel_launch(void* const* d_in, const int* in_sizes, int n_in,
                              void* d_out, int out_size) {
  const float* x    = (const float*)d_in[0];
  const float* eWih = (const float*)d_in[1];
  const float* eWhh = (const float*)d_in[2];
  const float* ebih = (const float*)d_in[3];
  const float* ebhh = (const float*)d_in[4];
  const float* dWih = (const float*)d_in[5];
  const float* dWhh = (const float*)d_in[6];
  const float* dbih = (const float*)d_in[7];
  const float* dbhh = (const float*)d_in[8];
  const float* dWhr = (const float*)d_in[9];
  float* out = (float*)d_out;

  init_kernel<<<8, 256>>>();
  tr_kernel<<<dim3(256, 15), dim3(32, 8)>>>(eWih);
  gx_kernel<<<dim3(32, 256), 256>>>(x, ebih, ebhh);
  weff_kernel<<<457, 128>>>(dWih, dWhh, dWhr);
  enc_kernel<<<NCTA, 256>>>(eWhh);
  dec_g0_kernel<<<229, 256>>>(dWih, dbih, dbhh);
  dec_kernel<<<DCTA, 256>>>(dbih, dbhh, out);
  softmax_kernel<<<SEQ, 512>>>(out);
}